// round 13
// baseline (speedup 1.0000x reference)
#include <cuda_runtime.h>
#include <cuda_fp16.h>
#include <cuda_fp8.h>
#include <cuda_bf16.h>

#define N_VERTS 100000
#define N_TETS  200000
#define BATCH   64
#define ROWS    (3 * N_VERTS)      // 300000

#define DET_BLOCKS 1184            // 8 CTAs/SM on 148 SMs
#define DET_THREADS 256
#define DET_STEP   (DET_BLOCKS * 16)

// batch permutation inside g_xTh/g_xTq: column j holds real batch sigma(j);
// sigma(t) = ((t&7)<<3)|(t>>3), self-inverse.
__device__ __forceinline__ int sigma6(int t) { return ((t & 7) << 3) | (t >> 3); }

__device__ __half g_xTh[(size_t)ROWS * BATCH];            // 38.4 MB fp16 (output path)
__device__ __nv_fp8_storage_t g_xTq[(size_t)ROWS * BATCH];// 19.2 MB e4m3 (det path)
__device__ float  g_partial[DET_BLOCKS * BATCH];
__device__ float  g_invscale[BATCH];                      // indexed by REAL batch
__device__ unsigned g_counter;                            // zero-init, self-resetting

// ---------------------------------------------------------------------------
// Transpose x[64][300000] -> xTh (fp16) + xTq (e4m3), batch-permuted by sigma.
// ---------------------------------------------------------------------------
__global__ void __launch_bounds__(512)
k_transpose(const float* __restrict__ x)
{
    __shared__ float4 tile4[64][33];
    const float* tile_f = (const float*)tile4;        // tile_f[b*132 + r]
    const int row0 = blockIdx.x * 128;

    // ---- fill: warp w, iter j: batch b=16j+w, LDG.128 of rows 4tx..4tx+3 ----
    const int tx = threadIdx.x & 31;
    const int w  = threadIdx.x >> 5;                  // 0..15
    const int r4 = row0 + 4 * tx;
    if (r4 < ROWS) {                                  // ROWS%4==0 -> quad fully valid
        #pragma unroll
        for (int j = 0; j < 4; j++) {
            const int b = j * 16 + w;
            tile4[b][tx] = __ldcs((const float4*)(x + (size_t)b * ROWS + r4));
        }
    }
    __syncthreads();

    // ---- drain: thread (g, rr): 8 LDS (banks 4g+rr, distinct)
    //      -> 1 STG.128 (fp16) + 1 STG.64 (fp8) ----
    const int g   = threadIdx.x & 7;
    const int rr0 = threadIdx.x >> 3;                 // 0..63
    #pragma unroll
    for (int p = 0; p < 2; p++) {
        const int rr  = rr0 + 64 * p;
        const int row = row0 + rr;
        if (row < ROWS) {
            __half h[8];
            __nv_fp8_storage_t q[8];
            #pragma unroll
            for (int k = 0; k < 8; k++) {
                const float f = tile_f[(8*k + g) * 132 + rr];
                h[k] = __float2half_rn(f);
                q[k] = __nv_cvt_float_to_fp8(f, __NV_SATFINITE, __NV_E4M3);
            }
            ((uint4*)(g_xTh + (size_t)row * 64))[g] = *(const uint4*)h;
            ((uint2*)(g_xTq + (size_t)row * 64))[g] = *(const uint2*)q;
        }
    }
}

// ---------------------------------------------------------------------------
// unsigned (4 e4m3) -> float4
// ---------------------------------------------------------------------------
__device__ __forceinline__ float4 q4f(unsigned u)
{
    __half2_raw r0 = __nv_cvt_fp8x2_to_halfraw2((__nv_fp8x2_storage_t)(u & 0xFFFFu), __NV_E4M3);
    __half2_raw r1 = __nv_cvt_fp8x2_to_halfraw2((__nv_fp8x2_storage_t)(u >> 16),     __NV_E4M3);
    float2 f0 = __half22float2(*(const __half2*)&r0);
    float2 f1 = __half22float2(*(const __half2*)&r1);
    return make_float4(f0.x, f0.y, f1.x, f1.y);
}

// ---------------------------------------------------------------------------
// Det kernel (e4m3 inputs): each warp handles 2 tets x 64 columns per iter.
// lane = (tetHalf, colGroup bg); lane loads 9 x LDG.32 (4 e4m3 each).
// fp32 accumulation; pipelined index loads; last-block epilogue.
// ---------------------------------------------------------------------------
__global__ void __launch_bounds__(DET_THREADS)
k_det(const int* __restrict__ M)
{
    __shared__ float sSum[8][64];
    __shared__ float sQ[4][64];
    __shared__ unsigned sTicket;

    const int wid  = threadIdx.x >> 5;
    const int lane = threadIdx.x & 31;
    const int half = lane >> 4;
    const int bg   = lane & 15;

    float acc0 = 0.f, acc1 = 0.f, acc2 = 0.f, acc3 = 0.f;

    int t = blockIdx.x * 16 + wid * 2 + half;         // < DET_STEP <= N_TETS
    int i0 = __ldg(M + 3 * t + 0);
    int i1 = __ldg(M + 3 * t + 1);
    int i2 = __ldg(M + 3 * t + 2);

    while (t < N_TETS) {
        const int tn = min(t + DET_STEP, N_TETS - 1);
        const int j0 = __ldg(M + 3 * tn + 0);
        const int j1 = __ldg(M + 3 * tn + 1);
        const int j2 = __ldg(M + 3 * tn + 2);

        const unsigned* pa = (const unsigned*)(g_xTq + (size_t)(3 * i0) * 64) + bg;
        const unsigned* pb = (const unsigned*)(g_xTq + (size_t)(3 * i1) * 64) + bg;
        const unsigned* pc = (const unsigned*)(g_xTq + (size_t)(3 * i2) * 64) + bg;

        // 9 independent LDG.32 — raw loads first so they batch
        unsigned ua0 = __ldg(pa), ua1 = __ldg(pa + 16), ua2 = __ldg(pa + 32);
        unsigned ub0 = __ldg(pb), ub1 = __ldg(pb + 16), ub2 = __ldg(pb + 32);
        unsigned uc0 = __ldg(pc), uc1 = __ldg(pc + 16), uc2 = __ldg(pc + 32);

        float4 ax = q4f(ua0), ay = q4f(ua1), az = q4f(ua2);
        float4 bx = q4f(ub0), by = q4f(ub1), bz = q4f(ub2);
        float4 cx = q4f(uc0), cy = q4f(uc1), cz = q4f(uc2);

        acc0 += fabsf(ax.x * (by.x * cz.x - bz.x * cy.x)
                    - ay.x * (bx.x * cz.x - bz.x * cx.x)
                    + az.x * (bx.x * cy.x - by.x * cx.x));
        acc1 += fabsf(ax.y * (by.y * cz.y - bz.y * cy.y)
                    - ay.y * (bx.y * cz.y - bz.y * cx.y)
                    + az.y * (bx.y * cy.y - by.y * cx.y));
        acc2 += fabsf(ax.z * (by.z * cz.z - bz.z * cy.z)
                    - ay.z * (bx.z * cz.z - bz.z * cx.z)
                    + az.z * (bx.z * cy.z - by.z * cx.z));
        acc3 += fabsf(ax.w * (by.w * cz.w - bz.w * cy.w)
                    - ay.w * (bx.w * cz.w - bz.w * cx.w)
                    + az.w * (bx.w * cy.w - by.w * cx.w));

        i0 = j0; i1 = j1; i2 = j2;
        t += DET_STEP;
    }

    acc0 += __shfl_down_sync(0xffffffffu, acc0, 16);
    acc1 += __shfl_down_sync(0xffffffffu, acc1, 16);
    acc2 += __shfl_down_sync(0xffffffffu, acc2, 16);
    acc3 += __shfl_down_sync(0xffffffffu, acc3, 16);
    if (lane < 16)
        ((float4*)sSum[wid])[bg] = make_float4(acc0, acc1, acc2, acc3);
    __syncthreads();

    if (threadIdx.x < 64) {
        float s = 0.f;
        #pragma unroll
        for (int w = 0; w < 8; w++) s += sSum[w][threadIdx.x];
        g_partial[blockIdx.x * 64 + threadIdx.x] = s;
    }
    __syncthreads();

    if (threadIdx.x == 0) {
        __threadfence();
        sTicket = atomicAdd(&g_counter, 1u);
    }
    __syncthreads();

    if (sTicket == DET_BLOCKS - 1) {
        __threadfence();
        {
            const int c = threadIdx.x & 63;
            const int q = threadIdx.x >> 6;
            const volatile float* p = g_partial;
            float s = 0.f;
            const int beg = q * (DET_BLOCKS / 4), end = beg + DET_BLOCKS / 4;
            for (int blk = beg; blk < end; blk++)
                s += p[blk * 64 + c];
            sQ[q][c] = s;
        }
        __syncthreads();
        if (threadIdx.x < 64) {
            float s = ((sQ[0][threadIdx.x] + sQ[1][threadIdx.x])
                     +  sQ[2][threadIdx.x]) + sQ[3][threadIdx.x];
            g_invscale[sigma6(threadIdx.x)] = 1.0f / cbrtf(s / 6.0f);
        }
        if (threadIdx.x == 0)
            g_counter = 0;
    }
}

// ---------------------------------------------------------------------------
// Output: read xTh (fp16, L2-hot), scale, inverse-transpose via conflict-free
// smem, write out[b][row] with coalesced float4 streaming stores.
// ---------------------------------------------------------------------------
__global__ void __launch_bounds__(512)
k_outT(float* __restrict__ out)
{
    __shared__ float tile_f[64 * 132];    // tile_f[real_batch*132 + r], 33 KB
    const int row0 = blockIdx.x * 128;

    const int g   = threadIdx.x & 7;
    const int rr0 = threadIdx.x >> 3;                 // 0..63
    float finv[8];
    #pragma unroll
    for (int k = 0; k < 8; k++)
        finv[k] = g_invscale[8*k + g];                // real batch of half k

    #pragma unroll
    for (int p = 0; p < 2; p++) {
        const int rr  = rr0 + 64 * p;
        const int row = row0 + rr;
        if (row < ROWS) {
            uint4 u = *((const uint4*)(g_xTh + (size_t)row * 64) + g);
            const __half2* h2 = (const __half2*)&u;
            #pragma unroll
            for (int k2 = 0; k2 < 4; k2++) {
                float2 f = __half22float2(h2[k2]);
                tile_f[(8*(2*k2+0) + g) * 132 + rr] = f.x * finv[2*k2+0];
                tile_f[(8*(2*k2+1) + g) * 132 + rr] = f.y * finv[2*k2+1];
            }
        }
    }
    __syncthreads();

    #pragma unroll
    for (int j = 0; j < 4; j++) {
        const int item = j * 512 + threadIdx.x;       // 0..2047
        const int b    = item >> 5;                   // real batch 0..63
        const int quad = item & 31;                   // row quad within tile
        const int row  = row0 + 4 * quad;
        if (row < ROWS) {
            float4 v = *(const float4*)(tile_f + b * 132 + 4 * quad);
            __stcs((float4*)(out + (size_t)b * ROWS + row), v);
        }
    }
}

// ---------------------------------------------------------------------------
extern "C" void kernel_launch(void* const* d_in, const int* in_sizes, int n_in,
                              void* d_out, int out_size)
{
    // x: 19,200,000 float32 ; M: 600,000 int32 — select by element count.
    const float* x;
    const int*   M;
    if (in_sizes[0] == 19200000) { x = (const float*)d_in[0]; M = (const int*)d_in[1]; }
    else                         { x = (const float*)d_in[1]; M = (const int*)d_in[0]; }
    float* o = (float*)d_out;

    const int tBlocks = (ROWS + 127) / 128;    // 2344
    k_transpose<<<tBlocks, 512>>>(x);
    k_det<<<DET_BLOCKS, DET_THREADS>>>(M);
    k_outT<<<tBlocks, 512>>>(o);
}

// round 14
// speedup vs baseline: 1.0588x; 1.0588x over previous
#include <cuda_runtime.h>
#include <cuda_fp16.h>
#include <cuda_bf16.h>

#define N_VERTS 100000
#define N_TETS  200000
#define BATCH   64
#define ROWS    (3 * N_VERTS)      // 300000

#define DET_BLOCKS 1184            // 8 CTAs/SM on 148 SMs
#define DET_THREADS 256
#define DET_STEP   (DET_BLOCKS * 16)

// batch permutation inside g_xTh: column j holds real batch sigma(j);
// sigma(t) = ((t&7)<<3)|(t>>3), self-inverse.
__device__ __forceinline__ int sigma6(int t) { return ((t & 7) << 3) | (t >> 3); }

__device__ __half g_xTh[(size_t)ROWS * BATCH];        // 38.4 MB fp16 transposed x
__device__ float  g_partial[DET_BLOCKS * BATCH];
__device__ float  g_invscale[BATCH];                  // indexed by REAL batch
__device__ unsigned g_counter;                        // zero-init, self-resetting

// ---------------------------------------------------------------------------
// Transpose x[64][300000] -> xTh[300000][64] (fp16, batch-permuted by sigma).
// ---------------------------------------------------------------------------
__global__ void __launch_bounds__(512)
k_transpose(const float* __restrict__ x)
{
    __shared__ float4 tile4[64][33];
    const float* tile_f = (const float*)tile4;        // tile_f[b*132 + r]
    const int row0 = blockIdx.x * 128;

    // ---- fill: warp w, iter j: batch b=16j+w, LDG.128 of rows 4tx..4tx+3 ----
    const int tx = threadIdx.x & 31;
    const int w  = threadIdx.x >> 5;                  // 0..15
    const int r4 = row0 + 4 * tx;
    if (r4 < ROWS) {                                  // ROWS%4==0 -> quad fully valid
        #pragma unroll
        for (int j = 0; j < 4; j++) {
            const int b = j * 16 + w;
            tile4[b][tx] = __ldcs((const float4*)(x + (size_t)b * ROWS + r4));
        }
    }
    __syncthreads();

    // ---- drain: thread (g, rr): 8 LDS (banks 4g+rr, distinct) -> STG.128 ----
    const int g   = threadIdx.x & 7;
    const int rr0 = threadIdx.x >> 3;                 // 0..63
    #pragma unroll
    for (int p = 0; p < 2; p++) {
        const int rr  = rr0 + 64 * p;
        const int row = row0 + rr;
        if (row < ROWS) {
            __half h[8];
            #pragma unroll
            for (int k = 0; k < 8; k++)
                h[k] = __float2half_rn(tile_f[(8*k + g) * 132 + rr]);
            ((uint4*)(g_xTh + (size_t)row * 64))[g] = *(const uint4*)h;
        }
    }
}

// ---------------------------------------------------------------------------
// uint2 (4 fp16) -> float4
// ---------------------------------------------------------------------------
__device__ __forceinline__ float4 h4f(uint2 u)
{
    float2 f0 = __half22float2(*(const __half2*)&u.x);
    float2 f1 = __half22float2(*(const __half2*)&u.y);
    return make_float4(f0.x, f0.y, f1.x, f1.y);
}

__device__ __forceinline__ void load9(int i0, int i1, int i2, int bg, uint2* U)
{
    const uint2* pa = (const uint2*)(g_xTh + (size_t)(3 * i0) * 64) + bg;
    const uint2* pb = (const uint2*)(g_xTh + (size_t)(3 * i1) * 64) + bg;
    const uint2* pc = (const uint2*)(g_xTh + (size_t)(3 * i2) * 64) + bg;
    U[0] = __ldg(pa); U[1] = __ldg(pa + 16); U[2] = __ldg(pa + 32);
    U[3] = __ldg(pb); U[4] = __ldg(pb + 16); U[5] = __ldg(pb + 32);
    U[6] = __ldg(pc); U[7] = __ldg(pc + 16); U[8] = __ldg(pc + 32);
}

// ---------------------------------------------------------------------------
// Det kernel, double-buffered: next tet-pair's indices AND 9 row loads are in
// flight while the current pair's determinants are computed -> ~2x in-flight
// bytes per warp, halving exposed L2 latency per iteration.
// ---------------------------------------------------------------------------
__global__ void __launch_bounds__(DET_THREADS)
k_det(const int* __restrict__ M)
{
    __shared__ float sSum[8][64];
    __shared__ float sQ[4][64];
    __shared__ unsigned sTicket;

    const int wid  = threadIdx.x >> 5;
    const int lane = threadIdx.x & 31;
    const int half = lane >> 4;
    const int bg   = lane & 15;

    float acc0 = 0.f, acc1 = 0.f, acc2 = 0.f, acc3 = 0.f;

    int t = blockIdx.x * 16 + wid * 2 + half;         // < DET_STEP <= N_TETS
    uint2 U[9];
    {
        const int i0 = __ldg(M + 3 * t + 0);
        const int i1 = __ldg(M + 3 * t + 1);
        const int i2 = __ldg(M + 3 * t + 2);
        load9(i0, i1, i2, bg, U);
    }

    while (true) {
        const int  tn   = t + DET_STEP;
        const bool more = (tn < N_TETS);
        const int  tc   = more ? tn : t;              // clamp (re-load cur rows)
        // prefetch next pair (indices then rows) while computing current
        const int j0 = __ldg(M + 3 * tc + 0);
        const int j1 = __ldg(M + 3 * tc + 1);
        const int j2 = __ldg(M + 3 * tc + 2);
        uint2 V[9];
        load9(j0, j1, j2, bg, V);

        float4 ax = h4f(U[0]), ay = h4f(U[1]), az = h4f(U[2]);
        float4 bx = h4f(U[3]), by = h4f(U[4]), bz = h4f(U[5]);
        float4 cx = h4f(U[6]), cy = h4f(U[7]), cz = h4f(U[8]);

        acc0 += fabsf(ax.x * (by.x * cz.x - bz.x * cy.x)
                    - ay.x * (bx.x * cz.x - bz.x * cx.x)
                    + az.x * (bx.x * cy.x - by.x * cx.x));
        acc1 += fabsf(ax.y * (by.y * cz.y - bz.y * cy.y)
                    - ay.y * (bx.y * cz.y - bz.y * cx.y)
                    + az.y * (bx.y * cy.y - by.y * cx.y));
        acc2 += fabsf(ax.z * (by.z * cz.z - bz.z * cy.z)
                    - ay.z * (bx.z * cz.z - bz.z * cx.z)
                    + az.z * (bx.z * cy.z - by.z * cx.z));
        acc3 += fabsf(ax.w * (by.w * cz.w - bz.w * cy.w)
                    - ay.w * (bx.w * cz.w - bz.w * cx.w)
                    + az.w * (bx.w * cy.w - by.w * cx.w));

        if (!more) break;
        #pragma unroll
        for (int k = 0; k < 9; k++) U[k] = V[k];
        t = tn;
    }

    acc0 += __shfl_down_sync(0xffffffffu, acc0, 16);
    acc1 += __shfl_down_sync(0xffffffffu, acc1, 16);
    acc2 += __shfl_down_sync(0xffffffffu, acc2, 16);
    acc3 += __shfl_down_sync(0xffffffffu, acc3, 16);
    if (lane < 16)
        ((float4*)sSum[wid])[bg] = make_float4(acc0, acc1, acc2, acc3);
    __syncthreads();

    if (threadIdx.x < 64) {
        float s = 0.f;
        #pragma unroll
        for (int w = 0; w < 8; w++) s += sSum[w][threadIdx.x];
        g_partial[blockIdx.x * 64 + threadIdx.x] = s;
    }
    __syncthreads();

    if (threadIdx.x == 0) {
        __threadfence();
        sTicket = atomicAdd(&g_counter, 1u);
    }
    __syncthreads();

    if (sTicket == DET_BLOCKS - 1) {
        __threadfence();
        {
            const int c = threadIdx.x & 63;
            const int q = threadIdx.x >> 6;
            const volatile float* p = g_partial;
            float s = 0.f;
            const int beg = q * (DET_BLOCKS / 4), end = beg + DET_BLOCKS / 4;
            for (int blk = beg; blk < end; blk++)
                s += p[blk * 64 + c];
            sQ[q][c] = s;
        }
        __syncthreads();
        if (threadIdx.x < 64) {
            float s = ((sQ[0][threadIdx.x] + sQ[1][threadIdx.x])
                     +  sQ[2][threadIdx.x]) + sQ[3][threadIdx.x];
            g_invscale[sigma6(threadIdx.x)] = 1.0f / cbrtf(s / 6.0f);
        }
        if (threadIdx.x == 0)
            g_counter = 0;
    }
}

// ---------------------------------------------------------------------------
// Output: read xTh (L2-hot), scale, inverse-transpose via conflict-free smem,
// write out[b][row] with coalesced float4 streaming stores.
// ---------------------------------------------------------------------------
__global__ void __launch_bounds__(512)
k_outT(float* __restrict__ out)
{
    __shared__ float tile_f[64 * 132];    // tile_f[real_batch*132 + r], 33 KB
    const int row0 = blockIdx.x * 128;

    const int g   = threadIdx.x & 7;
    const int rr0 = threadIdx.x >> 3;                 // 0..63
    float finv[8];
    #pragma unroll
    for (int k = 0; k < 8; k++)
        finv[k] = g_invscale[8*k + g];                // real batch of half k

    #pragma unroll
    for (int p = 0; p < 2; p++) {
        const int rr  = rr0 + 64 * p;
        const int row = row0 + rr;
        if (row < ROWS) {
            uint4 u = *((const uint4*)(g_xTh + (size_t)row * 64) + g);
            const __half2* h2 = (const __half2*)&u;
            #pragma unroll
            for (int k2 = 0; k2 < 4; k2++) {
                float2 f = __half22float2(h2[k2]);
                tile_f[(8*(2*k2+0) + g) * 132 + rr] = f.x * finv[2*k2+0];
                tile_f[(8*(2*k2+1) + g) * 132 + rr] = f.y * finv[2*k2+1];
            }
        }
    }
    __syncthreads();

    #pragma unroll
    for (int j = 0; j < 4; j++) {
        const int item = j * 512 + threadIdx.x;       // 0..2047
        const int b    = item >> 5;                   // real batch 0..63
        const int quad = item & 31;                   // row quad within tile
        const int row  = row0 + 4 * quad;
        if (row < ROWS) {
            float4 v = *(const float4*)(tile_f + b * 132 + 4 * quad);
            __stcs((float4*)(out + (size_t)b * ROWS + row), v);
        }
    }
}

// ---------------------------------------------------------------------------
extern "C" void kernel_launch(void* const* d_in, const int* in_sizes, int n_in,
                              void* d_out, int out_size)
{
    // x: 19,200,000 float32 ; M: 600,000 int32 — select by element count.
    const float* x;
    const int*   M;
    if (in_sizes[0] == 19200000) { x = (const float*)d_in[0]; M = (const int*)d_in[1]; }
    else                         { x = (const float*)d_in[1]; M = (const int*)d_in[0]; }
    float* o = (float*)d_out;

    const int tBlocks = (ROWS + 127) / 128;    // 2344
    k_transpose<<<tBlocks, 512>>>(x);
    k_det<<<DET_BLOCKS, DET_THREADS>>>(M);
    k_outT<<<tBlocks, 512>>>(o);
}